// round 4
// baseline (speedup 1.0000x reference)
#include <cuda_runtime.h>

#define N_NODES    100000
#define N_EDGES    1600000
#define HID        128
#define OUT_CH     10
#define NUM_GRAPHS 512

// ---------------- scratch (static device globals; referenced directly — the
// ONLY host API used in kernel_launch is kernel launches) --------------------
__device__ float g_h0[N_NODES * HID];
__device__ float g_h1[N_NODES * HID];
__device__ float g_z [N_NODES * HID];
__device__ int   g_rowptr[N_NODES + 1];
__device__ int   g_cnt[N_NODES];
__device__ int   g_local[N_NODES];
__device__ int   g_bsums[128];
__device__ int   g_col[N_EDGES];
__device__ int   g_start[NUM_GRAPHS + 1];

__device__ __forceinline__ const float* sel_buf(int sel, const float* ext) {
    if (sel == 0) return g_h0;
    if (sel == 1) return g_h1;
    return ext;
}

// ---------------- zero counters --------------------------------------------
__global__ void zero_cnt_kernel() {
    int i = blockIdx.x * blockDim.x + threadIdx.x;
    if (i < N_NODES) g_cnt[i] = 0;
}

// ---------------- CSR build (edge_index is int32: JAX x64 is disabled, so
// the reference's jnp.int64 silently demotes to int32) -----------------------
__global__ void hist_kernel(const int* __restrict__ ei) {
    int e = blockIdx.x * blockDim.x + threadIdx.x;
    if (e >= N_EDGES) return;
    int d = ei[N_EDGES + e];   // dst row
    atomicAdd(&g_cnt[d], 1);
}

__global__ void scan_local_kernel() {
    __shared__ int s[1024];
    int tid = threadIdx.x;
    int i = blockIdx.x * 1024 + tid;
    int v = (i < N_NODES) ? g_cnt[i] : 0;
    s[tid] = v;
    __syncthreads();
    for (int off = 1; off < 1024; off <<= 1) {
        int t = (tid >= off) ? s[tid - off] : 0;
        __syncthreads();
        s[tid] += t;
        __syncthreads();
    }
    if (i < N_NODES) g_local[i] = s[tid] - v;   // exclusive
    if (tid == 1023) g_bsums[blockIdx.x] = s[1023];
}

__global__ void scan_sums_kernel(int nb) {
    if (threadIdx.x == 0 && blockIdx.x == 0) {
        int run = 0;
        for (int i = 0; i < nb; i++) { int v = g_bsums[i]; g_bsums[i] = run; run += v; }
    }
}

__global__ void scan_add_kernel() {
    int i = blockIdx.x * blockDim.x + threadIdx.x;
    if (i < N_NODES) g_rowptr[i] = g_local[i] + g_bsums[i >> 10];
    if (i == 0) g_rowptr[N_NODES] = N_EDGES;
}

__global__ void fill_kernel(const int* __restrict__ ei) {
    int e = blockIdx.x * blockDim.x + threadIdx.x;
    if (e >= N_EDGES) return;
    int d = ei[N_EDGES + e];
    int s = ei[e];
    int pos = g_rowptr[d] + atomicAdd(&g_cnt[d], 1);   // g_cnt re-zeroed as cursor
    g_col[pos] = s;
}

// ---------------- aggregation: g_z = h + sum_{j in N(i)} h[j] --------------
__global__ __launch_bounds__(256) void aggregate_kernel(const float* __restrict__ x_ext,
                                                        int in_sel) {
    const float* __restrict__ h = sel_buf(in_sel, x_ext);
    int node = (blockIdx.x * blockDim.x + threadIdx.x) >> 5;
    int lane = threadIdx.x & 31;
    if (node >= N_NODES) return;
    int beg = g_rowptr[node];
    int end = g_rowptr[node + 1];
    int co = lane * 4;
    float4 acc = *(const float4*)(h + (size_t)node * HID + co);   // self term
    int e = beg;
    for (; e + 4 <= end; e += 4) {
        int s0 = g_col[e], s1 = g_col[e + 1], s2 = g_col[e + 2], s3 = g_col[e + 3];
        float4 v0 = *(const float4*)(h + (size_t)s0 * HID + co);
        float4 v1 = *(const float4*)(h + (size_t)s1 * HID + co);
        float4 v2 = *(const float4*)(h + (size_t)s2 * HID + co);
        float4 v3 = *(const float4*)(h + (size_t)s3 * HID + co);
        acc.x += v0.x + v1.x + v2.x + v3.x;
        acc.y += v0.y + v1.y + v2.y + v3.y;
        acc.z += v0.z + v1.z + v2.z + v3.z;
        acc.w += v0.w + v1.w + v2.w + v3.w;
    }
    for (; e < end; e++) {
        int s = g_col[e];
        float4 v = *(const float4*)(h + (size_t)s * HID + co);
        acc.x += v.x; acc.y += v.y; acc.z += v.z; acc.w += v.w;
    }
    *(float4*)(g_z + (size_t)node * HID + co) = acc;
}

// ---------------- fused MLP: out = [relu](relu(Z@W1+b1)@W2+b2) -------------
// 64 rows x 128 cols per block, 256 threads (16x16), 4x8 micro-tile.
// Static shared only (42KB < 48KB): A tile 64x132 (reused as H1), double-
// buffered 8k x 128n weight panel, biases.
#define MROWS 64

struct MlpSmem {
    float a[MROWS][132];       // 33.8KB, A tile (row-major), reused for H1
    float bp[2][8][128];       // 8KB weight panels
    float b1[128];
    float b2[128];
};

__device__ __forceinline__ void gemm_stage(MlpSmem& sm, const float* __restrict__ W,
                                           int ar, int bc, float acc[4][8]) {
#pragma unroll
    for (int i = 0; i < 4; i++)
#pragma unroll
        for (int j = 0; j < 8; j++) acc[i][j] = 0.f;

    int tid = threadIdx.x;
    int pr  = tid >> 5;          // 0..7 panel row
    int pc  = (tid & 31) << 2;   // 0..124 panel col (float4)

    // preload panel 0
    float4 nb = *(const float4*)(W + pr * 128 + pc);
    *(float4*)&sm.bp[0][pr][pc] = nb;
    __syncthreads();

#pragma unroll
    for (int kp = 0; kp < 16; kp++) {
        int buf = kp & 1;
        // prefetch next panel to registers (overlaps compute)
        if (kp < 15)
            nb = *(const float4*)(W + (kp + 1) * 8 * 128 + pr * 128 + pc);

#pragma unroll
        for (int kk = 0; kk < 8; kk += 4) {
            int k = kp * 8 + kk;
            float4 a4[4];
#pragma unroll
            for (int i = 0; i < 4; i++)
                a4[i] = *(const float4*)&sm.a[ar + i][k];
#pragma unroll
            for (int s = 0; s < 4; s++) {
                float4 b0 = *(const float4*)&sm.bp[buf][kk + s][bc];
                float4 b1 = *(const float4*)&sm.bp[buf][kk + s][bc + 4];
                float bb[8] = {b0.x, b0.y, b0.z, b0.w, b1.x, b1.y, b1.z, b1.w};
                float aa[4] = {a4[0].x, a4[1].x, a4[2].x, a4[3].x};
                if (s == 1) { aa[0] = a4[0].y; aa[1] = a4[1].y; aa[2] = a4[2].y; aa[3] = a4[3].y; }
                if (s == 2) { aa[0] = a4[0].z; aa[1] = a4[1].z; aa[2] = a4[2].z; aa[3] = a4[3].z; }
                if (s == 3) { aa[0] = a4[0].w; aa[1] = a4[1].w; aa[2] = a4[2].w; aa[3] = a4[3].w; }
#pragma unroll
                for (int i = 0; i < 4; i++)
#pragma unroll
                    for (int j = 0; j < 8; j++)
                        acc[i][j] += aa[i] * bb[j];
            }
        }
        __syncthreads();
        if (kp < 15) {
            *(float4*)&sm.bp[buf ^ 1][pr][pc] = nb;
            __syncthreads();
        }
    }
}

__global__ __launch_bounds__(256) void mlp_kernel(const float* __restrict__ W1,
                                                  const float* __restrict__ B1,
                                                  const float* __restrict__ W2,
                                                  const float* __restrict__ B2,
                                                  int out_sel, int reluOut) {
    __shared__ MlpSmem sm;
    float* O = (out_sel == 0) ? g_h0 : g_h1;

    int tid = threadIdx.x;
    int tx = tid & 15;           // col group: bc = tx*8
    int ty = tid >> 4;           // row group: ar = ty*4
    int ar = ty * 4, bc = tx * 8;
    int row0 = blockIdx.x * MROWS;

    // load A tile (Z) row-major; 64*32 float4, each thread 8
    {
#pragma unroll
        for (int p = 0; p < 8; p++) {
            int idx = p * 256 + tid;          // 0..2047
            int r = idx >> 5;                 // 0..63
            int c4 = (idx & 31) << 2;         // 0..124
            float4 v = make_float4(0.f, 0.f, 0.f, 0.f);
            if (row0 + r < N_NODES)
                v = *(const float4*)(g_z + (size_t)(row0 + r) * HID + c4);
            *(float4*)&sm.a[r][c4] = v;
        }
        if (tid < 128) { sm.b1[tid] = B1[tid]; sm.b2[tid] = B2[tid]; }
    }
    __syncthreads();

    float acc[4][8];

    // ---- stage 1: Z @ W1 ----
    gemm_stage(sm, W1, ar, bc, acc);
    __syncthreads();   // all A reads done before overwrite as H1

    // relu(acc + b1) -> H1 in sm.a
#pragma unroll
    for (int j = 0; j < 8; j++) {
        float bb = sm.b1[bc + j];
#pragma unroll
        for (int i = 0; i < 4; i++)
            sm.a[ar + i][bc + j] = fmaxf(acc[i][j] + bb, 0.f);
    }
    __syncthreads();

    // ---- stage 2: H1 @ W2 ----
    gemm_stage(sm, W2, ar, bc, acc);

    // epilogue
#pragma unroll
    for (int i = 0; i < 4; i++) {
        int r = row0 + ar + i;
        if (r < N_NODES) {
#pragma unroll
            for (int j0 = 0; j0 < 8; j0 += 4) {
                float4 o;
                o.x = acc[i][j0 + 0] + sm.b2[bc + j0 + 0];
                o.y = acc[i][j0 + 1] + sm.b2[bc + j0 + 1];
                o.z = acc[i][j0 + 2] + sm.b2[bc + j0 + 2];
                o.w = acc[i][j0 + 3] + sm.b2[bc + j0 + 3];
                if (reluOut) {
                    o.x = fmaxf(o.x, 0.f); o.y = fmaxf(o.y, 0.f);
                    o.z = fmaxf(o.z, 0.f); o.w = fmaxf(o.w, 0.f);
                }
                *(float4*)(O + (size_t)r * HID + bc + j0) = o;
            }
        }
    }
}

// ---------------- pooling boundaries (batch is sorted int32) ---------------
__global__ void boundaries_kernel(const int* __restrict__ batch) {
    int i = blockIdx.x * blockDim.x + threadIdx.x;
    if (i >= N_NODES) return;
    int b = batch[i];
    if (i == 0) {
        for (int g = 0; g <= b; g++) g_start[g] = 0;
    } else {
        int p = batch[i - 1];
        if (p < b)
            for (int g = p + 1; g <= b; g++) g_start[g] = i;
    }
    if (i == N_NODES - 1) {
        for (int g = b + 1; g <= NUM_GRAPHS; g++) g_start[g] = N_NODES;
    }
}

// ---------------- fused global_add_pool + final linear ---------------------
__global__ void pool_final_kernel(const float* __restrict__ lw,
                                  const float* __restrict__ lb,
                                  float* __restrict__ out,
                                  int in_sel) {
    const float* __restrict__ h = (in_sel == 0) ? g_h0 : g_h1;
    int g = blockIdx.x;
    int c = threadIdx.x;   // 128 threads
    int s = g_start[g], e = g_start[g + 1];
    float acc = 0.f;
    for (int n = s; n < e; n++) acc += h[(size_t)n * HID + c];
    __shared__ float sp[HID];
    sp[c] = acc;
    __syncthreads();
    if (c < OUT_CH) {
        float o = lb[c];
#pragma unroll 8
        for (int k = 0; k < HID; k++) o += sp[k] * lw[k * OUT_CH + c];
        out[g * OUT_CH + c] = o;
    }
}

// ---------------- host: kernel launches ONLY -------------------------------
extern "C" void kernel_launch(void* const* d_in, const int* in_sizes, int n_in,
                              void* d_out, int out_size) {
    const float* x     = (const float*)d_in[0];
    const int*   ei    = (const int*)d_in[1];     // int32 (JAX x64 disabled)
    const int*   batch = (const int*)d_in[2];     // int32
    const float* w1[3] = {(const float*)d_in[3],  (const float*)d_in[7],  (const float*)d_in[11]};
    const float* b1[3] = {(const float*)d_in[4],  (const float*)d_in[8],  (const float*)d_in[12]};
    const float* w2[3] = {(const float*)d_in[5],  (const float*)d_in[9],  (const float*)d_in[13]};
    const float* b2[3] = {(const float*)d_in[6],  (const float*)d_in[10], (const float*)d_in[14]};
    const float* lin_w = (const float*)d_in[15];
    const float* lin_b = (const float*)d_in[16];
    float* out = (float*)d_out;

    // ---- CSR build (deterministic per launch) ----
    zero_cnt_kernel<<<(N_NODES + 255) / 256, 256>>>();
    hist_kernel<<<(N_EDGES + 255) / 256, 256>>>(ei);
    scan_local_kernel<<<(N_NODES + 1023) / 1024, 1024>>>();
    scan_sums_kernel<<<1, 32>>>((N_NODES + 1023) / 1024);
    scan_add_kernel<<<(N_NODES + 255) / 256, 256>>>();
    zero_cnt_kernel<<<(N_NODES + 255) / 256, 256>>>();
    fill_kernel<<<(N_EDGES + 255) / 256, 256>>>(ei);
    boundaries_kernel<<<(N_NODES + 255) / 256, 256>>>(batch);

    // ---- 3 GIN layers ----
    const int agg_blocks = (N_NODES * 32 + 255) / 256;
    const int mlp_blocks = (N_NODES + MROWS - 1) / MROWS;

    // layer 0: src = x (ext), dst = g_h0
    aggregate_kernel<<<agg_blocks, 256>>>(x, -1);
    mlp_kernel<<<mlp_blocks, 256>>>(w1[0], b1[0], w2[0], b2[0], 0, 1);
    // layer 1: src = g_h0, dst = g_h1
    aggregate_kernel<<<agg_blocks, 256>>>(nullptr, 0);
    mlp_kernel<<<mlp_blocks, 256>>>(w1[1], b1[1], w2[1], b2[1], 1, 1);
    // layer 2: src = g_h1, dst = g_h0 (no final relu)
    aggregate_kernel<<<agg_blocks, 256>>>(nullptr, 1);
    mlp_kernel<<<mlp_blocks, 256>>>(w1[2], b1[2], w2[2], b2[2], 0, 0);

    // ---- pool + final linear ----
    pool_final_kernel<<<NUM_GRAPHS, 128>>>(lin_w, lin_b, out, 0);
}

// round 6
// speedup vs baseline: 1.7427x; 1.7427x over previous
#include <cuda_runtime.h>
#include <cuda_bf16.h>
#include <stdint.h>

#define N_NODES    100000
#define N_EDGES    1600000
#define HID        128
#define OUT_CH     10
#define NUM_GRAPHS 512

// ---------------- scratch (static device globals; kernel launches are the
// ONLY host API used in kernel_launch) ---------------------------------------
__device__ float g_h0[N_NODES * HID];
__device__ float g_h1[N_NODES * HID];
__device__ float g_z [N_NODES * HID];
__device__ int   g_rowptr[N_NODES + 1];
__device__ int   g_cnt[N_NODES];
__device__ int   g_local[N_NODES];
__device__ int   g_bsums[128];
__device__ int   g_col[N_EDGES];
__device__ int   g_start[NUM_GRAPHS + 1];

__device__ __forceinline__ const float* sel_buf(int sel, const float* ext) {
    if (sel == 0) return g_h0;
    if (sel == 1) return g_h1;
    return ext;
}

__device__ __forceinline__ void split_bf16(float x, __nv_bfloat16& h, __nv_bfloat16& l) {
    h = __float2bfloat16(x);
    l = __float2bfloat16(x - __bfloat162float(h));
}
__device__ __forceinline__ uint32_t pack2(__nv_bfloat16 lo, __nv_bfloat16 hi) {
    return (uint32_t)__bfloat16_as_ushort(lo) | ((uint32_t)__bfloat16_as_ushort(hi) << 16);
}
__device__ __forceinline__ void mma_bf16(float c[4], uint32_t a0, uint32_t a1,
                                         uint32_t a2, uint32_t a3,
                                         uint32_t b0, uint32_t b1) {
    asm volatile(
        "mma.sync.aligned.m16n8k16.row.col.f32.bf16.bf16.f32 "
        "{%0,%1,%2,%3}, {%4,%5,%6,%7}, {%8,%9}, {%0,%1,%2,%3};\n"
        : "+f"(c[0]), "+f"(c[1]), "+f"(c[2]), "+f"(c[3])
        : "r"(a0), "r"(a1), "r"(a2), "r"(a3), "r"(b0), "r"(b1));
}

// ---------------- zero counters --------------------------------------------
__global__ void zero_cnt_kernel() {
    int i = blockIdx.x * blockDim.x + threadIdx.x;
    if (i < N_NODES) g_cnt[i] = 0;
}

// ---------------- CSR build (edge_index is int32) ---------------------------
__global__ void hist_kernel(const int* __restrict__ ei) {
    int e = blockIdx.x * blockDim.x + threadIdx.x;
    if (e >= N_EDGES) return;
    atomicAdd(&g_cnt[ei[N_EDGES + e]], 1);
}

__global__ void scan_local_kernel() {
    __shared__ int s[1024];
    int tid = threadIdx.x;
    int i = blockIdx.x * 1024 + tid;
    int v = (i < N_NODES) ? g_cnt[i] : 0;
    s[tid] = v;
    __syncthreads();
    for (int off = 1; off < 1024; off <<= 1) {
        int t = (tid >= off) ? s[tid - off] : 0;
        __syncthreads();
        s[tid] += t;
        __syncthreads();
    }
    if (i < N_NODES) g_local[i] = s[tid] - v;
    if (tid == 1023) g_bsums[blockIdx.x] = s[1023];
}

__global__ void scan_sums_kernel(int nb) {
    if (threadIdx.x == 0 && blockIdx.x == 0) {
        int run = 0;
        for (int i = 0; i < nb; i++) { int v = g_bsums[i]; g_bsums[i] = run; run += v; }
    }
}

__global__ void scan_add_kernel() {
    int i = blockIdx.x * blockDim.x + threadIdx.x;
    if (i < N_NODES) g_rowptr[i] = g_local[i] + g_bsums[i >> 10];
    if (i == 0) g_rowptr[N_NODES] = N_EDGES;
}

__global__ void fill_kernel(const int* __restrict__ ei) {
    int e = blockIdx.x * blockDim.x + threadIdx.x;
    if (e >= N_EDGES) return;
    int d = ei[N_EDGES + e];
    int s = ei[e];
    int pos = g_rowptr[d] + atomicAdd(&g_cnt[d], 1);
    g_col[pos] = s;
}

// ---------------- aggregation: g_z = h + sum_{j in N(i)} h[j] --------------
__global__ __launch_bounds__(256) void aggregate_kernel(const float* __restrict__ x_ext,
                                                        int in_sel) {
    const float* __restrict__ h = sel_buf(in_sel, x_ext);
    int node = (blockIdx.x * blockDim.x + threadIdx.x) >> 5;
    int lane = threadIdx.x & 31;
    if (node >= N_NODES) return;
    int beg = g_rowptr[node];
    int end = g_rowptr[node + 1];
    int co = lane * 4;
    float4 acc = *(const float4*)(h + (size_t)node * HID + co);
    int e = beg;
    for (; e + 4 <= end; e += 4) {
        int s0 = g_col[e], s1 = g_col[e + 1], s2 = g_col[e + 2], s3 = g_col[e + 3];
        float4 v0 = *(const float4*)(h + (size_t)s0 * HID + co);
        float4 v1 = *(const float4*)(h + (size_t)s1 * HID + co);
        float4 v2 = *(const float4*)(h + (size_t)s2 * HID + co);
        float4 v3 = *(const float4*)(h + (size_t)s3 * HID + co);
        acc.x += v0.x + v1.x + v2.x + v3.x;
        acc.y += v0.y + v1.y + v2.y + v3.y;
        acc.z += v0.z + v1.z + v2.z + v3.z;
        acc.w += v0.w + v1.w + v2.w + v3.w;
    }
    for (; e < end; e++) {
        int s = g_col[e];
        float4 v = *(const float4*)(h + (size_t)s * HID + co);
        acc.x += v.x; acc.y += v.y; acc.z += v.z; acc.w += v.w;
    }
    *(float4*)(g_z + (size_t)node * HID + co) = acc;
}

// ============ HMMA MLP: bf16 hi/lo 3-term, mma.sync m16n8k16 ================
// Block: 64 nodes x 128 out-ch, 256 threads = 8 warps (2m x 4n), warp 32x32.
// SMEM (words): A_hi[64][68], A_lo[64][68] (kpair-packed, reused for H1),
// W panel hi/lo [128][9] (k=16 per panel), biases. Total 45,056 B static.
#define A_ST  68
#define WB_ST 9
#define A_HI  0
#define A_LO  4352
#define WB_HI 8704
#define WB_LO 9856
#define BS1   11008
#define BS2   11136
#define SM_WORDS 11264

__device__ __forceinline__ void mma_stage(uint32_t* sm, const float* __restrict__ W,
                                          int tid, int gid, int tig, int m0, int n0,
                                          float acc[2][4][4]) {
#pragma unroll 1
    for (int p = 0; p < 8; p++) {
        // prefetch panel p to regs: 4 items of (n, kp_local)
        float w0[4], w1[4];
#pragma unroll
        for (int it = 0; it < 4; it++) {
            int i = it * 256 + tid;
            int n = i & 127, kpl = i >> 7;
            int kg = p * 16 + kpl * 2;
            w0[it] = W[kg * HID + n];
            w1[it] = W[(kg + 1) * HID + n];
        }
        __syncthreads();   // previous panel fully consumed
#pragma unroll
        for (int it = 0; it < 4; it++) {
            int i = it * 256 + tid;
            int n = i & 127, kpl = i >> 7;
            __nv_bfloat16 h0, l0, h1, l1;
            split_bf16(w0[it], h0, l0);
            split_bf16(w1[it], h1, l1);
            sm[WB_HI + n * WB_ST + kpl] = pack2(h0, h1);
            sm[WB_LO + n * WB_ST + kpl] = pack2(l0, l1);
        }
        __syncthreads();   // panel visible

        // A fragments for this k-step (kpairs p*8 .. p*8+7)
        uint32_t ah[2][4], al[2][4];
#pragma unroll
        for (int mt = 0; mt < 2; mt++) {
            int base = (m0 + mt * 16 + gid) * A_ST + p * 8;
            ah[mt][0] = sm[A_HI + base + tig];
            ah[mt][1] = sm[A_HI + base + 8 * A_ST + tig];
            ah[mt][2] = sm[A_HI + base + 4 + tig];
            ah[mt][3] = sm[A_HI + base + 8 * A_ST + 4 + tig];
            al[mt][0] = sm[A_LO + base + tig];
            al[mt][1] = sm[A_LO + base + 8 * A_ST + tig];
            al[mt][2] = sm[A_LO + base + 4 + tig];
            al[mt][3] = sm[A_LO + base + 8 * A_ST + 4 + tig];
        }
#pragma unroll
        for (int nt = 0; nt < 4; nt++) {
            int nb = (n0 + nt * 8 + gid) * WB_ST;
            uint32_t b0h = sm[WB_HI + nb + tig];
            uint32_t b1h = sm[WB_HI + nb + 4 + tig];
            uint32_t b0l = sm[WB_LO + nb + tig];
            uint32_t b1l = sm[WB_LO + nb + 4 + tig];
#pragma unroll
            for (int mt = 0; mt < 2; mt++) {
                mma_bf16(acc[mt][nt], ah[mt][0], ah[mt][1], ah[mt][2], ah[mt][3], b0h, b1h);
                mma_bf16(acc[mt][nt], ah[mt][0], ah[mt][1], ah[mt][2], ah[mt][3], b0l, b1l);
                mma_bf16(acc[mt][nt], al[mt][0], al[mt][1], al[mt][2], al[mt][3], b0h, b1h);
            }
        }
    }
}

__global__ __launch_bounds__(256, 2) void mlp_mma_kernel(const float* __restrict__ W1,
                                                         const float* __restrict__ B1,
                                                         const float* __restrict__ W2,
                                                         const float* __restrict__ B2,
                                                         int out_sel, int reluOut) {
    __shared__ uint32_t sm[SM_WORDS];
    float* O = (out_sel == 0) ? g_h0 : g_h1;
    float* bs1 = (float*)(sm + BS1);
    float* bs2 = (float*)(sm + BS2);

    int tid  = threadIdx.x;
    int lane = tid & 31, warp = tid >> 5;
    int gid  = lane >> 2, tig = lane & 3;
    int m0   = (warp & 1) * 32;
    int n0   = (warp >> 1) * 32;
    int row0 = blockIdx.x * 64;

    if (tid < 128) { bs1[tid] = B1[tid]; bs2[tid] = B2[tid]; }

    // ---- load Z tile, hi/lo split, kpair-packed ----
#pragma unroll
    for (int p = 0; p < 8; p++) {
        int idx = p * 256 + tid;          // 0..2047
        int r  = idx >> 5;                // node row 0..63
        int c4 = (idx & 31) << 2;         // channel 0..124
        float4 v = make_float4(0.f, 0.f, 0.f, 0.f);
        if (row0 + r < N_NODES)
            v = *(const float4*)(g_z + (size_t)(row0 + r) * HID + c4);
        int kp = c4 >> 1;
        __nv_bfloat16 hx, lx, hy, ly, hz, lz, hw, lw;
        split_bf16(v.x, hx, lx); split_bf16(v.y, hy, ly);
        split_bf16(v.z, hz, lz); split_bf16(v.w, hw, lw);
        sm[A_HI + r * A_ST + kp]     = pack2(hx, hy);
        sm[A_HI + r * A_ST + kp + 1] = pack2(hz, hw);
        sm[A_LO + r * A_ST + kp]     = pack2(lx, ly);
        sm[A_LO + r * A_ST + kp + 1] = pack2(lz, lw);
    }

    float acc[2][4][4];
#pragma unroll
    for (int mt = 0; mt < 2; mt++)
#pragma unroll
        for (int nt = 0; nt < 4; nt++)
#pragma unroll
            for (int q = 0; q < 4; q++) acc[mt][nt][q] = 0.f;

    // ---- stage 1 (first panel-sync also publishes the A tile) ----
    mma_stage(sm, W1, tid, gid, tig, m0, n0, acc);

    // ---- epilogue 1: bias+relu, write H1 over A (all stage-1 reads done) ----
    __syncthreads();
#pragma unroll
    for (int mt = 0; mt < 2; mt++) {
#pragma unroll
        for (int nt = 0; nt < 4; nt++) {
            int col = n0 + nt * 8 + 2 * tig;
            float bia0 = bs1[col], bia1 = bs1[col + 1];
            int kp2 = ((n0 + nt * 8) >> 1) + tig;
            int ra = m0 + mt * 16 + gid;
            float v0 = fmaxf(acc[mt][nt][0] + bia0, 0.f);
            float v1 = fmaxf(acc[mt][nt][1] + bia1, 0.f);
            float v2 = fmaxf(acc[mt][nt][2] + bia0, 0.f);
            float v3 = fmaxf(acc[mt][nt][3] + bia1, 0.f);
            __nv_bfloat16 h0, l0, h1, l1, h2, l2, h3, l3;
            split_bf16(v0, h0, l0); split_bf16(v1, h1, l1);
            split_bf16(v2, h2, l2); split_bf16(v3, h3, l3);
            sm[A_HI + ra * A_ST + kp2]       = pack2(h0, h1);
            sm[A_LO + ra * A_ST + kp2]       = pack2(l0, l1);
            sm[A_HI + (ra + 8) * A_ST + kp2] = pack2(h2, h3);
            sm[A_LO + (ra + 8) * A_ST + kp2] = pack2(l2, l3);
#pragma unroll
            for (int q = 0; q < 4; q++) acc[mt][nt][q] = 0.f;
        }
    }
    // stage 2's first __syncthreads orders these writes before panel store;
    // A-frag reads happen after the second barrier.

    // ---- stage 2 ----
    mma_stage(sm, W2, tid, gid, tig, m0, n0, acc);

    // ---- epilogue 2: bias (+relu), float2 STG ----
#pragma unroll
    for (int mt = 0; mt < 2; mt++) {
#pragma unroll
        for (int nt = 0; nt < 4; nt++) {
            int col = n0 + nt * 8 + 2 * tig;
            float bia0 = bs2[col], bia1 = bs2[col + 1];
            int node0 = row0 + m0 + mt * 16 + gid;
            float2 o0, o1;
            o0.x = acc[mt][nt][0] + bia0; o0.y = acc[mt][nt][1] + bia1;
            o1.x = acc[mt][nt][2] + bia0; o1.y = acc[mt][nt][3] + bia1;
            if (reluOut) {
                o0.x = fmaxf(o0.x, 0.f); o0.y = fmaxf(o0.y, 0.f);
                o1.x = fmaxf(o1.x, 0.f); o1.y = fmaxf(o1.y, 0.f);
            }
            if (node0 < N_NODES)
                *(float2*)(O + (size_t)node0 * HID + col) = o0;
            if (node0 + 8 < N_NODES)
                *(float2*)(O + (size_t)(node0 + 8) * HID + col) = o1;
        }
    }
}

// ---------------- pooling boundaries (batch is sorted int32) ---------------
__global__ void boundaries_kernel(const int* __restrict__ batch) {
    int i = blockIdx.x * blockDim.x + threadIdx.x;
    if (i >= N_NODES) return;
    int b = batch[i];
    if (i == 0) {
        for (int g = 0; g <= b; g++) g_start[g] = 0;
    } else {
        int p = batch[i - 1];
        if (p < b)
            for (int g = p + 1; g <= b; g++) g_start[g] = i;
    }
    if (i == N_NODES - 1) {
        for (int g = b + 1; g <= NUM_GRAPHS; g++) g_start[g] = N_NODES;
    }
}

// ---------------- fused global_add_pool + final linear ---------------------
__global__ void pool_final_kernel(const float* __restrict__ lw,
                                  const float* __restrict__ lb,
                                  float* __restrict__ out,
                                  int in_sel) {
    const float* __restrict__ h = (in_sel == 0) ? g_h0 : g_h1;
    int g = blockIdx.x;
    int c = threadIdx.x;   // 128 threads
    int s = g_start[g], e = g_start[g + 1];
    float acc = 0.f;
    for (int n = s; n < e; n++) acc += h[(size_t)n * HID + c];
    __shared__ float sp[HID];
    sp[c] = acc;
    __syncthreads();
    if (c < OUT_CH) {
        float o = lb[c];
#pragma unroll 8
        for (int k = 0; k < HID; k++) o += sp[k] * lw[k * OUT_CH + c];
        out[g * OUT_CH + c] = o;
    }
}

// ---------------- host: kernel launches ONLY -------------------------------
extern "C" void kernel_launch(void* const* d_in, const int* in_sizes, int n_in,
                              void* d_out, int out_size) {
    const float* x     = (const float*)d_in[0];
    const int*   ei    = (const int*)d_in[1];     // int32 (JAX x64 disabled)
    const int*   batch = (const int*)d_in[2];     // int32
    const float* w1[3] = {(const float*)d_in[3],  (const float*)d_in[7],  (const float*)d_in[11]};
    const float* b1[3] = {(const float*)d_in[4],  (const float*)d_in[8],  (const float*)d_in[12]};
    const float* w2[3] = {(const float*)d_in[5],  (const float*)d_in[9],  (const float*)d_in[13]};
    const float* b2[3] = {(const float*)d_in[6],  (const float*)d_in[10], (const float*)d_in[14]};
    const float* lin_w = (const float*)d_in[15];
    const float* lin_b = (const float*)d_in[16];
    float* out = (float*)d_out;

    // ---- CSR build (deterministic per launch) ----
    zero_cnt_kernel<<<(N_NODES + 255) / 256, 256>>>();
    hist_kernel<<<(N_EDGES + 255) / 256, 256>>>(ei);
    scan_local_kernel<<<(N_NODES + 1023) / 1024, 1024>>>();
    scan_sums_kernel<<<1, 32>>>((N_NODES + 1023) / 1024);
    scan_add_kernel<<<(N_NODES + 255) / 256, 256>>>();
    zero_cnt_kernel<<<(N_NODES + 255) / 256, 256>>>();
    fill_kernel<<<(N_EDGES + 255) / 256, 256>>>(ei);
    boundaries_kernel<<<(N_NODES + 255) / 256, 256>>>(batch);

    // ---- 3 GIN layers ----
    const int agg_blocks = (N_NODES * 32 + 255) / 256;
    const int mlp_blocks = (N_NODES + 63) / 64;

    aggregate_kernel<<<agg_blocks, 256>>>(x, -1);
    mlp_mma_kernel<<<mlp_blocks, 256>>>(w1[0], b1[0], w2[0], b2[0], 0, 1);
    aggregate_kernel<<<agg_blocks, 256>>>(nullptr, 0);
    mlp_mma_kernel<<<mlp_blocks, 256>>>(w1[1], b1[1], w2[1], b2[1], 1, 1);
    aggregate_kernel<<<agg_blocks, 256>>>(nullptr, 1);
    mlp_mma_kernel<<<mlp_blocks, 256>>>(w1[2], b1[2], w2[2], b2[2], 0, 0);

    // ---- pool + final linear ----
    pool_final_kernel<<<NUM_GRAPHS, 128>>>(lin_w, lin_b, out, 0);
}